// round 4
// baseline (speedup 1.0000x reference)
#include <cuda_runtime.h>
#include <math.h>

// Problem constants
#define BB   2
#define SS   2048
#define LL   1024
#define HH   16
#define HKK  4
#define DD   64
#define MROWS (BB*SS)          // 4096
#define QKVN  ((HH + 2*HKK)*DD) // 1536 (only the used columns of w_qkv)

// Scratch (allocation-free rule: __device__ globals)
__device__ float g_qkv [MROWS * QKVN];   // [4096][1536]: q(1024) | k(256) | v(256)
__device__ float g_attn[MROWS * LL];     // [4096][1024]: attention output, head-major

// ---------------------------------------------------------------------------
// SGEMM (NT): C[M,N] = A[M,K] * B[N,K]^T ; M,N multiples of 128, K mult of 8.
// 128x128 block tile, BK=8, 256 threads, 8x8 register tile per thread.
// ---------------------------------------------------------------------------
__device__ __forceinline__
void sgemm_nt_body(const float* __restrict__ A, const float* __restrict__ B,
                   float* __restrict__ C, int M, int N, int K)
{
    __shared__ float As[8][128];
    __shared__ float Bs[8][128];

    const int bm  = blockIdx.y << 7;
    const int bn  = blockIdx.x << 7;
    const int tid = threadIdx.x;
    const int tx  = tid & 15;
    const int ty  = tid >> 4;
    const int lr  = tid >> 1;          // 0..127
    const int lc  = (tid & 1) << 2;    // 0 or 4

    const float* Ap = A + (size_t)(bm + lr) * K + lc;
    const float* Bp = B + (size_t)(bn + lr) * K + lc;

    float acc[8][8];
#pragma unroll
    for (int i = 0; i < 8; i++)
#pragma unroll
        for (int j = 0; j < 8; j++) acc[i][j] = 0.f;

    for (int k0 = 0; k0 < K; k0 += 8) {
        float4 a4 = *(const float4*)(Ap + k0);
        float4 b4 = *(const float4*)(Bp + k0);
        As[lc+0][lr] = a4.x; As[lc+1][lr] = a4.y;
        As[lc+2][lr] = a4.z; As[lc+3][lr] = a4.w;
        Bs[lc+0][lr] = b4.x; Bs[lc+1][lr] = b4.y;
        Bs[lc+2][lr] = b4.z; Bs[lc+3][lr] = b4.w;
        __syncthreads();
#pragma unroll
        for (int k = 0; k < 8; k++) {
            float ar[8], br[8];
            *(float4*)(ar)     = *(const float4*)(&As[k][ty*8]);
            *(float4*)(ar + 4) = *(const float4*)(&As[k][ty*8 + 4]);
            *(float4*)(br)     = *(const float4*)(&Bs[k][tx*8]);
            *(float4*)(br + 4) = *(const float4*)(&Bs[k][tx*8 + 4]);
#pragma unroll
            for (int i = 0; i < 8; i++)
#pragma unroll
                for (int j = 0; j < 8; j++)
                    acc[i][j] = fmaf(ar[i], br[j], acc[i][j]);
        }
        __syncthreads();
    }

#pragma unroll
    for (int i = 0; i < 8; i++) {
        float* cp = C + (size_t)(bm + ty*8 + i) * N + bn + tx*8;
        *(float4*)(cp)     = make_float4(acc[i][0], acc[i][1], acc[i][2], acc[i][3]);
        *(float4*)(cp + 4) = make_float4(acc[i][4], acc[i][5], acc[i][6], acc[i][7]);
    }
}

// GEMM 1: qkv = x @ w_qkv[0:1536]^T  (writes device-global scratch)
__global__ __launch_bounds__(256, 2)
void qkv_gemm_kernel(const float* __restrict__ A, const float* __restrict__ B)
{
    sgemm_nt_body(A, B, g_qkv, MROWS, QKVN, LL);
}

// GEMM 2: out = attn @ w_out^T  (reads device-global scratch)
__global__ __launch_bounds__(256, 2)
void out_gemm_kernel(const float* __restrict__ B, float* __restrict__ C)
{
    sgemm_nt_body(g_attn, B, C, MROWS, LL, LL);
}

// ---------------------------------------------------------------------------
// Flash attention, causal, fp32.
// grid = (S/64, H, B), block = 256 threads (16x16 logical).
// Each thread owns a 4x4 tile of the 64x64 score block and a 4x4 tile of the
// 64x64 output block (rows = ty*4.., cols = tx*4..). m/l stats are kept
// redundantly in registers by each of the 16 threads of a row group, so no
// shared-memory state / no races. Smem = exactly 48 KB (P reuses K^T buffer).
// ---------------------------------------------------------------------------
__global__ __launch_bounds__(256)
void attn_kernel()
{
    __shared__ float Qs [64][64];   // Q[r][d], pre-scaled by 1/sqrt(D)
    __shared__ float KPs[64][64];   // first K^T[d][c], later P[r][c]
    __shared__ float Vs [64][64];   // V[c][d]

    const int qb  = blockIdx.x;     // query block 0..31
    const int h   = blockIdx.y;     // head 0..15
    const int b   = blockIdx.z;     // batch 0..1
    const int hk  = h >> 2;         // GQA group (H/HK = 4)
    const int tid = threadIdx.x;
    const int tx  = tid & 15;
    const int ty  = tid >> 4;
    const int r0  = ty * 4;
    const int c0  = tx * 4;

    // ---- load + pre-scale Q tile ----
    {
        const float* qbase = g_qkv + ((size_t)(b * SS + qb * 64)) * QKVN + h * DD;
        for (int t = tid; t < 1024; t += 256) {
            int r = t >> 4;
            int c = (t & 15) << 2;
            float4 v = *(const float4*)(qbase + (size_t)r * QKVN + c);
            Qs[r][c + 0] = v.x * 0.125f;
            Qs[r][c + 1] = v.y * 0.125f;
            Qs[r][c + 2] = v.z * 0.125f;
            Qs[r][c + 3] = v.w * 0.125f;
        }
    }

    float m_i[4], l_i[4], o_acc[4][4];
#pragma unroll
    for (int i = 0; i < 4; i++) {
        m_i[i] = -1e30f;
        l_i[i] = 0.f;
#pragma unroll
        for (int j = 0; j < 4; j++) o_acc[i][j] = 0.f;
    }
    __syncthreads();

    for (int kb = 0; kb <= qb; kb++) {
        // ---- load K (transposed into KPs) and V ----
        const float* kbase = g_qkv + ((size_t)(b * SS + kb * 64)) * QKVN
                             + HH * DD + hk * DD;   // k starts at col 1024
        for (int t = tid; t < 1024; t += 256) {
            int r = t >> 4;               // key index within block
            int c = (t & 15) << 2;        // d offset
            float4 kv = *(const float4*)(kbase + (size_t)r * QKVN + c);
            KPs[c + 0][r] = kv.x; KPs[c + 1][r] = kv.y;
            KPs[c + 2][r] = kv.z; KPs[c + 3][r] = kv.w;
            float4 vv = *(const float4*)(kbase + HKK * DD + (size_t)r * QKVN + c);
            *(float4*)(&Vs[r][c]) = vv;   // v is 256 floats after k
        }
        __syncthreads();

        // ---- S = Q K^T (64x64), 4x4 per thread ----
        float s[4][4];
#pragma unroll
        for (int i = 0; i < 4; i++)
#pragma unroll
            for (int j = 0; j < 4; j++) s[i][j] = 0.f;

#pragma unroll 8
        for (int d = 0; d < 64; d++) {
            float a[4];
#pragma unroll
            for (int i = 0; i < 4; i++) a[i] = Qs[r0 + i][d];
            float4 bv = *(const float4*)(&KPs[d][c0]);
#pragma unroll
            for (int i = 0; i < 4; i++) {
                s[i][0] = fmaf(a[i], bv.x, s[i][0]);
                s[i][1] = fmaf(a[i], bv.y, s[i][1]);
                s[i][2] = fmaf(a[i], bv.z, s[i][2]);
                s[i][3] = fmaf(a[i], bv.w, s[i][3]);
            }
        }

        // ---- causal mask (diagonal block only) ----
        if (kb == qb) {
#pragma unroll
            for (int i = 0; i < 4; i++)
#pragma unroll
                for (int j = 0; j < 4; j++)
                    if (c0 + j > r0 + i) s[i][j] = -1e30f;
        }

        // ---- online softmax (row stats replicated across 16-lane groups) ----
#pragma unroll
        for (int i = 0; i < 4; i++) {
            float mx = fmaxf(fmaxf(s[i][0], s[i][1]), fmaxf(s[i][2], s[i][3]));
#pragma unroll
            for (int o = 1; o < 16; o <<= 1)
                mx = fmaxf(mx, __shfl_xor_sync(0xffffffffu, mx, o));
            float mnew = fmaxf(m_i[i], mx);
            float sum = 0.f;
#pragma unroll
            for (int j = 0; j < 4; j++) {
                s[i][j] = __expf(s[i][j] - mnew);
                sum += s[i][j];
            }
#pragma unroll
            for (int o = 1; o < 16; o <<= 1)
                sum += __shfl_xor_sync(0xffffffffu, sum, o);
            float alpha = __expf(m_i[i] - mnew);   // 0 on first block (-1e30)
            l_i[i] = l_i[i] * alpha + sum;
            m_i[i] = mnew;
#pragma unroll
            for (int j = 0; j < 4; j++) o_acc[i][j] *= alpha;
        }

        __syncthreads();   // everyone done reading KPs as K^T
#pragma unroll
        for (int i = 0; i < 4; i++)
            *(float4*)(&KPs[r0 + i][c0]) =
                make_float4(s[i][0], s[i][1], s[i][2], s[i][3]);
        __syncthreads();   // P visible to all

        // ---- O += P V ----
#pragma unroll 8
        for (int c = 0; c < 64; c++) {
            float a[4];
#pragma unroll
            for (int i = 0; i < 4; i++) a[i] = KPs[r0 + i][c];
            float4 bv = *(const float4*)(&Vs[c][c0]);
#pragma unroll
            for (int i = 0; i < 4; i++) {
                o_acc[i][0] = fmaf(a[i], bv.x, o_acc[i][0]);
                o_acc[i][1] = fmaf(a[i], bv.y, o_acc[i][1]);
                o_acc[i][2] = fmaf(a[i], bv.z, o_acc[i][2]);
                o_acc[i][3] = fmaf(a[i], bv.w, o_acc[i][3]);
            }
        }
        __syncthreads();   // before next iteration overwrites tiles
    }

    // ---- normalize + store (head-major [b,s,h,d]) ----
    float* obase = g_attn + ((size_t)(b * SS + qb * 64)) * LL + h * DD + c0;
#pragma unroll
    for (int i = 0; i < 4; i++) {
        float inv = 1.f / l_i[i];
        *(float4*)(obase + (size_t)(r0 + i) * LL) =
            make_float4(o_acc[i][0] * inv, o_acc[i][1] * inv,
                        o_acc[i][2] * inv, o_acc[i][3] * inv);
    }
}

// ---------------------------------------------------------------------------
extern "C" void kernel_launch(void* const* d_in, const int* in_sizes, int n_in,
                              void* d_out, int out_size)
{
    // Identify inputs by element count (all distinct):
    //   x: 2*2048*1024 = 4194304, w_qkv: 3584*1024 = 3670016, w_out: 1024*1024 = 1048576
    const float* x = nullptr;
    const float* w_qkv = nullptr;
    const float* w_out = nullptr;
    for (int i = 0; i < n_in; i++) {
        if      (in_sizes[i] == 4194304) x     = (const float*)d_in[i];
        else if (in_sizes[i] == 3670016) w_qkv = (const float*)d_in[i];
        else if (in_sizes[i] == 1048576) w_out = (const float*)d_in[i];
    }
    float* out = (float*)d_out;

    dim3 blk(256);

    // 1) fused QKV projection (only the 1536 columns actually consumed)
    qkv_gemm_kernel<<<dim3(QKVN / 128, MROWS / 128), blk>>>(x, w_qkv);

    // 2) causal GQA flash attention
    attn_kernel<<<dim3(SS / 64, HH, BB), blk>>>();

    // 3) output projection
    out_gemm_kernel<<<dim3(LL / 128, MROWS / 128), blk>>>(w_out, out);
}

// round 5
// speedup vs baseline: 2.8282x; 2.8282x over previous
#include <cuda_runtime.h>
#include <math.h>

// Problem constants
#define BB   2
#define SS   2048
#define LL   1024
#define HH   16
#define HKK  4
#define DD   64
#define MROWS (BB*SS)            // 4096
#define QKVN  ((HH + 2*HKK)*DD)  // 1536 (only the used columns of w_qkv)

// Scratch (allocation-free rule: __device__ globals)
__device__ float g_qkv [MROWS * QKVN];   // [4096][1536]: q(1024) | k(256) | v(256)
__device__ float g_attn[MROWS * LL];     // [4096][1024]: attention output, head-major

// ---------------------------------------------------------------------------
// TF32 helpers
// ---------------------------------------------------------------------------
__device__ __forceinline__ unsigned f2tf(float f) {
    unsigned u;
    asm("cvt.rna.tf32.f32 %0, %1;" : "=r"(u) : "f"(f));
    return u;
}

// D += A*B, m16n8k8 tf32. a[4], b[2], c[4] per PTX fragment layouts.
__device__ __forceinline__ void mma8(float* c, const unsigned* a, const unsigned* b) {
    asm volatile(
        "mma.sync.aligned.m16n8k8.row.col.f32.tf32.tf32.f32 "
        "{%0,%1,%2,%3}, {%4,%5,%6,%7}, {%8,%9}, {%0,%1,%2,%3};"
        : "+f"(c[0]), "+f"(c[1]), "+f"(c[2]), "+f"(c[3])
        : "r"(a[0]), "r"(a[1]), "r"(a[2]), "r"(a[3]),
          "r"(b[0]), "r"(b[1]));
}

// ---------------------------------------------------------------------------
// TF32 tensor-core GEMM (NT): C[M,N] = A[M,K] * B[N,K]^T
// 128x128 block, BK=16, 256 threads, warps 2(M)x4(N) -> 64x32 warp tiles.
// Smem row stride 20 (16+4) => fragment LDS.32 pattern is bank-conflict-free:
// bank = (20*g + t4 + 8*ks) mod 32 hits all 32 banks.
// ---------------------------------------------------------------------------
#define BKS 20

__device__ __forceinline__
void mma_gemm_nt(const float* __restrict__ A, const float* __restrict__ B,
                 float* __restrict__ C, int N, int K)
{
    __shared__ unsigned As[2][128 * BKS];
    __shared__ unsigned Bs[2][128 * BKS];

    const int bm   = blockIdx.y << 7;
    const int bn   = blockIdx.x << 7;
    const int tid  = threadIdx.x;
    const int lane = tid & 31;
    const int wid  = tid >> 5;
    const int wm   = wid >> 2;     // 0..1
    const int wn   = wid & 3;      // 0..3
    const int g    = lane >> 2;    // 0..7
    const int t4   = lane & 3;     // 0..3

    // gmem staging: 512 float4 per tile, 2 per thread
    const int r0 = tid >> 2;             // 0..63
    const int c0 = (tid & 3) << 2;       // 0,4,8,12
    const float* Ag0 = A + (size_t)(bm + r0)      * K + c0;
    const float* Ag1 = A + (size_t)(bm + r0 + 64) * K + c0;
    const float* Bg0 = B + (size_t)(bn + r0)      * K + c0;
    const float* Bg1 = B + (size_t)(bn + r0 + 64) * K + c0;

    float acc[4][4][4];
#pragma unroll
    for (int mt = 0; mt < 4; mt++)
#pragma unroll
        for (int nt = 0; nt < 4; nt++)
#pragma unroll
            for (int r = 0; r < 4; r++) acc[mt][nt][r] = 0.f;

    const int NT = K >> 4;

    float4 va0 = *(const float4*)(Ag0);
    float4 va1 = *(const float4*)(Ag1);
    float4 vb0 = *(const float4*)(Bg0);
    float4 vb1 = *(const float4*)(Bg1);
    {
        unsigned* d;
        d = &As[0][r0 * BKS + c0];
        d[0]=f2tf(va0.x); d[1]=f2tf(va0.y); d[2]=f2tf(va0.z); d[3]=f2tf(va0.w);
        d = &As[0][(r0 + 64) * BKS + c0];
        d[0]=f2tf(va1.x); d[1]=f2tf(va1.y); d[2]=f2tf(va1.z); d[3]=f2tf(va1.w);
        d = &Bs[0][r0 * BKS + c0];
        d[0]=f2tf(vb0.x); d[1]=f2tf(vb0.y); d[2]=f2tf(vb0.z); d[3]=f2tf(vb0.w);
        d = &Bs[0][(r0 + 64) * BKS + c0];
        d[0]=f2tf(vb1.x); d[1]=f2tf(vb1.y); d[2]=f2tf(vb1.z); d[3]=f2tf(vb1.w);
    }
    __syncthreads();

    for (int kt = 0; kt < NT; kt++) {
        const int cur = kt & 1;
        if (kt + 1 < NT) {
            const int ko = (kt + 1) << 4;
            va0 = *(const float4*)(Ag0 + ko);
            va1 = *(const float4*)(Ag1 + ko);
            vb0 = *(const float4*)(Bg0 + ko);
            vb1 = *(const float4*)(Bg1 + ko);
        }
        const unsigned* as = As[cur];
        const unsigned* bs = Bs[cur];

#pragma unroll
        for (int ks = 0; ks < 2; ks++) {
            const int kb = ks * 8;
            unsigned af[4][4], bf[4][2];
#pragma unroll
            for (int mt = 0; mt < 4; mt++) {
                const int row = wm * 64 + mt * 16 + g;
                af[mt][0] = as[ row      * BKS + kb + t4];
                af[mt][1] = as[(row + 8) * BKS + kb + t4];
                af[mt][2] = as[ row      * BKS + kb + t4 + 4];
                af[mt][3] = as[(row + 8) * BKS + kb + t4 + 4];
            }
#pragma unroll
            for (int nt = 0; nt < 4; nt++) {
                const int nr = wn * 32 + nt * 8 + g;
                bf[nt][0] = bs[nr * BKS + kb + t4];
                bf[nt][1] = bs[nr * BKS + kb + t4 + 4];
            }
#pragma unroll
            for (int mt = 0; mt < 4; mt++)
#pragma unroll
                for (int nt = 0; nt < 4; nt++)
                    mma8(acc[mt][nt], af[mt], bf[nt]);
        }

        if (kt + 1 < NT) {
            const int nb = (kt + 1) & 1;
            unsigned* d;
            d = &As[nb][r0 * BKS + c0];
            d[0]=f2tf(va0.x); d[1]=f2tf(va0.y); d[2]=f2tf(va0.z); d[3]=f2tf(va0.w);
            d = &As[nb][(r0 + 64) * BKS + c0];
            d[0]=f2tf(va1.x); d[1]=f2tf(va1.y); d[2]=f2tf(va1.z); d[3]=f2tf(va1.w);
            d = &Bs[nb][r0 * BKS + c0];
            d[0]=f2tf(vb0.x); d[1]=f2tf(vb0.y); d[2]=f2tf(vb0.z); d[3]=f2tf(vb0.w);
            d = &Bs[nb][(r0 + 64) * BKS + c0];
            d[0]=f2tf(vb1.x); d[1]=f2tf(vb1.y); d[2]=f2tf(vb1.z); d[3]=f2tf(vb1.w);
            __syncthreads();
        }
    }

    // epilogue
#pragma unroll
    for (int mt = 0; mt < 4; mt++) {
        const int row = bm + wm * 64 + mt * 16 + g;
#pragma unroll
        for (int nt = 0; nt < 4; nt++) {
            const int col = bn + wn * 32 + nt * 8 + 2 * t4;
            *(float2*)(C + (size_t)row * N + col) =
                make_float2(acc[mt][nt][0], acc[mt][nt][1]);
            *(float2*)(C + (size_t)(row + 8) * N + col) =
                make_float2(acc[mt][nt][2], acc[mt][nt][3]);
        }
    }
}

__global__ __launch_bounds__(256)
void qkv_gemm_kernel(const float* __restrict__ x, const float* __restrict__ w)
{
    mma_gemm_nt(x, w, g_qkv, QKVN, LL);
}

__global__ __launch_bounds__(256)
void out_gemm_kernel(const float* __restrict__ w, float* __restrict__ out)
{
    mma_gemm_nt(g_attn, w, out, LL, LL);
}

// ---------------------------------------------------------------------------
// Flash attention, causal, TF32 tensor cores.
// grid = (S/64, H, B), 128 threads = 4 warps. Warp w owns rows 16w..16w+15
// of the 64x64 S/O tiles (one m16 strip, all 64 columns = 8 n-tiles).
// Online softmax on C-fragments, reduced across quads via shfl.
// Smem (dynamic, stride 68 => conflict-free fragment LDS):
//   Qs[64][68] (prescaled), Ks[64][68] (reused for P), Vt[64(d)][68(key)].
// ---------------------------------------------------------------------------
#define AST 68
#define ATTN_SMEM (3 * 64 * AST * 4)

__global__ __launch_bounds__(128)
void attn_kernel()
{
    extern __shared__ unsigned sm[];
    unsigned* Qs = sm;
    unsigned* Ks = sm + 64 * AST;       // K^T operand, later P
    unsigned* Vt = sm + 2 * 64 * AST;   // V transposed: Vt[d][key]

    const int qb   = blockIdx.x;
    const int h    = blockIdx.y;
    const int b    = blockIdx.z;
    const int hk   = h >> 2;
    const int tid  = threadIdx.x;
    const int lane = tid & 31;
    const int w    = tid >> 5;
    const int g    = lane >> 2;
    const int t4   = lane & 3;
    const int R0   = 16 * w + g;        // fragment row (R1 = R0 + 8)

    // ---- load + prescale Q ----
    {
        const float* qbase = g_qkv + (size_t)(b * SS + qb * 64) * QKVN + h * DD;
#pragma unroll
        for (int i = 0; i < 8; i++) {
            const int e = tid + i * 128;
            const int r = e >> 4, c = (e & 15) << 2;
            float4 v = *(const float4*)(qbase + (size_t)r * QKVN + c);
            unsigned* d = &Qs[r * AST + c];
            d[0] = f2tf(v.x * 0.125f); d[1] = f2tf(v.y * 0.125f);
            d[2] = f2tf(v.z * 0.125f); d[3] = f2tf(v.w * 0.125f);
        }
    }

    float m0 = -1e30f, m1 = -1e30f, l0 = 0.f, l1 = 0.f;
    float oacc[8][4];
#pragma unroll
    for (int nt = 0; nt < 8; nt++)
#pragma unroll
        for (int r = 0; r < 4; r++) oacc[nt][r] = 0.f;

    __syncthreads();

    for (int kb = 0; kb <= qb; kb++) {
        // ---- load K and V^T ----
        const float* kbase = g_qkv + (size_t)(b * SS + kb * 64) * QKVN
                             + HH * DD + hk * DD;
#pragma unroll
        for (int i = 0; i < 8; i++) {
            const int e = tid + i * 128;
            const int r = e >> 4, c = (e & 15) << 2;
            float4 kv = *(const float4*)(kbase + (size_t)r * QKVN + c);
            unsigned* d = &Ks[r * AST + c];
            d[0] = f2tf(kv.x); d[1] = f2tf(kv.y);
            d[2] = f2tf(kv.z); d[3] = f2tf(kv.w);
            float4 vv = *(const float4*)(kbase + HKK * DD + (size_t)r * QKVN + c);
            Vt[(c + 0) * AST + r] = f2tf(vv.x);
            Vt[(c + 1) * AST + r] = f2tf(vv.y);
            Vt[(c + 2) * AST + r] = f2tf(vv.z);
            Vt[(c + 3) * AST + r] = f2tf(vv.w);
        }
        __syncthreads();

        // ---- S = Q K^T (warp strip: m16 x n64) ----
        float sacc[8][4];
#pragma unroll
        for (int nt = 0; nt < 8; nt++)
#pragma unroll
            for (int r = 0; r < 4; r++) sacc[nt][r] = 0.f;

#pragma unroll
        for (int kk = 0; kk < 8; kk++) {
            const int kp = kk * 8;
            unsigned af[4];
            af[0] = Qs[ R0      * AST + kp + t4];
            af[1] = Qs[(R0 + 8) * AST + kp + t4];
            af[2] = Qs[ R0      * AST + kp + t4 + 4];
            af[3] = Qs[(R0 + 8) * AST + kp + t4 + 4];
#pragma unroll
            for (int nt = 0; nt < 8; nt++) {
                unsigned bf[2];
                bf[0] = Ks[(nt * 8 + g) * AST + kp + t4];
                bf[1] = Ks[(nt * 8 + g) * AST + kp + t4 + 4];
                mma8(sacc[nt], af, bf);
            }
        }

        // ---- causal mask (diagonal block) ----
        if (kb == qb) {
#pragma unroll
            for (int nt = 0; nt < 8; nt++) {
                const int cc = nt * 8 + 2 * t4;
                if (cc     > R0)     sacc[nt][0] = -1e30f;
                if (cc + 1 > R0)     sacc[nt][1] = -1e30f;
                if (cc     > R0 + 8) sacc[nt][2] = -1e30f;
                if (cc + 1 > R0 + 8) sacc[nt][3] = -1e30f;
            }
        }

        // ---- online softmax (rows R0, R0+8; reduce across quad) ----
        float mx0 = -1e30f, mx1 = -1e30f;
#pragma unroll
        for (int nt = 0; nt < 8; nt++) {
            mx0 = fmaxf(mx0, fmaxf(sacc[nt][0], sacc[nt][1]));
            mx1 = fmaxf(mx1, fmaxf(sacc[nt][2], sacc[nt][3]));
        }
        mx0 = fmaxf(mx0, __shfl_xor_sync(0xffffffffu, mx0, 1));
        mx0 = fmaxf(mx0, __shfl_xor_sync(0xffffffffu, mx0, 2));
        mx1 = fmaxf(mx1, __shfl_xor_sync(0xffffffffu, mx1, 1));
        mx1 = fmaxf(mx1, __shfl_xor_sync(0xffffffffu, mx1, 2));

        const float mn0 = fmaxf(m0, mx0);
        const float mn1 = fmaxf(m1, mx1);
        float sum0 = 0.f, sum1 = 0.f;
#pragma unroll
        for (int nt = 0; nt < 8; nt++) {
            sacc[nt][0] = __expf(sacc[nt][0] - mn0);
            sacc[nt][1] = __expf(sacc[nt][1] - mn0);
            sacc[nt][2] = __expf(sacc[nt][2] - mn1);
            sacc[nt][3] = __expf(sacc[nt][3] - mn1);
            sum0 += sacc[nt][0] + sacc[nt][1];
            sum1 += sacc[nt][2] + sacc[nt][3];
        }
        sum0 += __shfl_xor_sync(0xffffffffu, sum0, 1);
        sum0 += __shfl_xor_sync(0xffffffffu, sum0, 2);
        sum1 += __shfl_xor_sync(0xffffffffu, sum1, 1);
        sum1 += __shfl_xor_sync(0xffffffffu, sum1, 2);

        const float a0 = __expf(m0 - mn0);   // 0 on first iteration
        const float a1 = __expf(m1 - mn1);
        l0 = l0 * a0 + sum0;  m0 = mn0;
        l1 = l1 * a1 + sum1;  m1 = mn1;
#pragma unroll
        for (int nt = 0; nt < 8; nt++) {
            oacc[nt][0] *= a0; oacc[nt][1] *= a0;
            oacc[nt][2] *= a1; oacc[nt][3] *= a1;
        }

        __syncthreads();   // all warps finished reading Ks as K

        // ---- store P into Ks (own rows only) ----
#pragma unroll
        for (int nt = 0; nt < 8; nt++) {
            const int cc = nt * 8 + 2 * t4;
            Ks[ R0      * AST + cc    ] = f2tf(sacc[nt][0]);
            Ks[ R0      * AST + cc + 1] = f2tf(sacc[nt][1]);
            Ks[(R0 + 8) * AST + cc    ] = f2tf(sacc[nt][2]);
            Ks[(R0 + 8) * AST + cc + 1] = f2tf(sacc[nt][3]);
        }
        __syncwarp();      // P rows consumed only by this warp

        // ---- O += P * V  (A = P rows, B = Vt[d][key]) ----
#pragma unroll
        for (int kk = 0; kk < 8; kk++) {
            const int kp = kk * 8;
            unsigned af[4];
            af[0] = Ks[ R0      * AST + kp + t4];
            af[1] = Ks[(R0 + 8) * AST + kp + t4];
            af[2] = Ks[ R0      * AST + kp + t4 + 4];
            af[3] = Ks[(R0 + 8) * AST + kp + t4 + 4];
#pragma unroll
            for (int nt = 0; nt < 8; nt++) {
                unsigned bf[2];
                bf[0] = Vt[(nt * 8 + g) * AST + kp + t4];
                bf[1] = Vt[(nt * 8 + g) * AST + kp + t4 + 4];
                mma8(oacc[nt], af, bf);
            }
        }
        __syncthreads();   // before next iteration overwrites Ks/Vt
    }

    // ---- normalize + store (head-major [b,s,h,d]) ----
    const float inv0 = 1.f / l0;
    const float inv1 = 1.f / l1;
    float* ob = g_attn + (size_t)(b * SS + qb * 64) * LL + h * DD;
#pragma unroll
    for (int nt = 0; nt < 8; nt++) {
        const int cc = nt * 8 + 2 * t4;
        *(float2*)(ob + (size_t)R0 * LL + cc) =
            make_float2(oacc[nt][0] * inv0, oacc[nt][1] * inv0);
        *(float2*)(ob + (size_t)(R0 + 8) * LL + cc) =
            make_float2(oacc[nt][2] * inv1, oacc[nt][3] * inv1);
    }
}

// ---------------------------------------------------------------------------
extern "C" void kernel_launch(void* const* d_in, const int* in_sizes, int n_in,
                              void* d_out, int out_size)
{
    const float* x = nullptr;
    const float* w_qkv = nullptr;
    const float* w_out = nullptr;
    for (int i = 0; i < n_in; i++) {
        if      (in_sizes[i] == 4194304) x     = (const float*)d_in[i];
        else if (in_sizes[i] == 3670016) w_qkv = (const float*)d_in[i];
        else if (in_sizes[i] == 1048576) w_out = (const float*)d_in[i];
    }
    float* out = (float*)d_out;

    static bool attr_set = false;
    if (!attr_set) {
        cudaFuncSetAttribute(attn_kernel,
                             cudaFuncAttributeMaxDynamicSharedMemorySize,
                             ATTN_SMEM);
        attr_set = true;
    }

    // 1) fused QKV projection (only the 1536 columns actually consumed)
    qkv_gemm_kernel<<<dim3(QKVN / 128, MROWS / 128), 256>>>(x, w_qkv);

    // 2) causal GQA flash attention (tf32 tensor cores)
    attn_kernel<<<dim3(SS / 64, HH, BB), 128, ATTN_SMEM>>>();

    // 3) output projection
    out_gemm_kernel<<<dim3(LL / 128, MROWS / 128), 256>>>(w_out, out);
}

// round 6
// speedup vs baseline: 3.5199x; 1.2446x over previous
#include <cuda_runtime.h>
#include <math.h>

// Problem constants
#define BB   2
#define SS   2048
#define LL   1024
#define HH   16
#define HKK  4
#define DD   64
#define MROWS (BB*SS)            // 4096
#define QKVN  ((HH + 2*HKK)*DD)  // 1536 (only the used columns of w_qkv)

// Scratch (allocation-free rule: __device__ globals)
__device__ float g_qkv [MROWS * QKVN];   // [4096][1536]: q(1024) | k(256) | v(256)
__device__ float g_attn[MROWS * LL];     // [4096][1024]: attention output, head-major

// ---------------------------------------------------------------------------
// TF32 helpers
// ---------------------------------------------------------------------------
__device__ __forceinline__ unsigned f2tf(float f) {
    unsigned u;
    asm("cvt.rna.tf32.f32 %0, %1;" : "=r"(u) : "f"(f));
    return u;
}

__device__ __forceinline__ void mma8(float* c, const unsigned* a, const unsigned* b) {
    asm volatile(
        "mma.sync.aligned.m16n8k8.row.col.f32.tf32.tf32.f32 "
        "{%0,%1,%2,%3}, {%4,%5,%6,%7}, {%8,%9}, {%0,%1,%2,%3};"
        : "+f"(c[0]), "+f"(c[1]), "+f"(c[2]), "+f"(c[3])
        : "r"(a[0]), "r"(a[1]), "r"(a[2]), "r"(a[3]),
          "r"(b[0]), "r"(b[1]));
}

// ---------------------------------------------------------------------------
// TF32 tensor-core GEMM (NT): C[M,N] = A[M,K] * B[N,K]^T
// 128x128 block, BK=16, 256 threads, warps 2(M)x4(N) -> 64x32 warp tiles.
// Smem row stride 20: fragment LDS.32 banks (20g+t4) mod 32 all distinct;
// staging STS.128 phases cover all 32 banks.
// ---------------------------------------------------------------------------
#define BKS 20

__device__ __forceinline__
void mma_gemm_nt(const float* __restrict__ A, const float* __restrict__ B,
                 float* __restrict__ C, int N, int K)
{
    __shared__ unsigned As[2][128 * BKS];
    __shared__ unsigned Bs[2][128 * BKS];

    const int bm   = blockIdx.y << 7;
    const int bn   = blockIdx.x << 7;
    const int tid  = threadIdx.x;
    const int lane = tid & 31;
    const int wid  = tid >> 5;
    const int wm   = wid >> 2;     // 0..1
    const int wn   = wid & 3;      // 0..3
    const int g    = lane >> 2;    // 0..7
    const int t4   = lane & 3;     // 0..3

    const int r0 = tid >> 2;             // 0..63
    const int c0 = (tid & 3) << 2;       // 0,4,8,12
    const float* Ag0 = A + (size_t)(bm + r0)      * K + c0;
    const float* Ag1 = A + (size_t)(bm + r0 + 64) * K + c0;
    const float* Bg0 = B + (size_t)(bn + r0)      * K + c0;
    const float* Bg1 = B + (size_t)(bn + r0 + 64) * K + c0;

    float acc[4][4][4];
#pragma unroll
    for (int mt = 0; mt < 4; mt++)
#pragma unroll
        for (int nt = 0; nt < 4; nt++)
#pragma unroll
            for (int r = 0; r < 4; r++) acc[mt][nt][r] = 0.f;

    const int NT = K >> 4;

    float4 va0 = *(const float4*)(Ag0);
    float4 va1 = *(const float4*)(Ag1);
    float4 vb0 = *(const float4*)(Bg0);
    float4 vb1 = *(const float4*)(Bg1);
    {
        *(uint4*)(&As[0][r0 * BKS + c0]) =
            make_uint4(f2tf(va0.x), f2tf(va0.y), f2tf(va0.z), f2tf(va0.w));
        *(uint4*)(&As[0][(r0 + 64) * BKS + c0]) =
            make_uint4(f2tf(va1.x), f2tf(va1.y), f2tf(va1.z), f2tf(va1.w));
        *(uint4*)(&Bs[0][r0 * BKS + c0]) =
            make_uint4(f2tf(vb0.x), f2tf(vb0.y), f2tf(vb0.z), f2tf(vb0.w));
        *(uint4*)(&Bs[0][(r0 + 64) * BKS + c0]) =
            make_uint4(f2tf(vb1.x), f2tf(vb1.y), f2tf(vb1.z), f2tf(vb1.w));
    }
    __syncthreads();

    for (int kt = 0; kt < NT; kt++) {
        const int cur = kt & 1;
        if (kt + 1 < NT) {
            const int ko = (kt + 1) << 4;
            va0 = *(const float4*)(Ag0 + ko);
            va1 = *(const float4*)(Ag1 + ko);
            vb0 = *(const float4*)(Bg0 + ko);
            vb1 = *(const float4*)(Bg1 + ko);
        }
        const unsigned* as = As[cur];
        const unsigned* bs = Bs[cur];

#pragma unroll
        for (int ks = 0; ks < 2; ks++) {
            const int kb = ks * 8;
            unsigned af[4][4], bf[4][2];
#pragma unroll
            for (int mt = 0; mt < 4; mt++) {
                const int row = wm * 64 + mt * 16 + g;
                af[mt][0] = as[ row      * BKS + kb + t4];
                af[mt][1] = as[(row + 8) * BKS + kb + t4];
                af[mt][2] = as[ row      * BKS + kb + t4 + 4];
                af[mt][3] = as[(row + 8) * BKS + kb + t4 + 4];
            }
#pragma unroll
            for (int nt = 0; nt < 4; nt++) {
                const int nr = wn * 32 + nt * 8 + g;
                bf[nt][0] = bs[nr * BKS + kb + t4];
                bf[nt][1] = bs[nr * BKS + kb + t4 + 4];
            }
#pragma unroll
            for (int mt = 0; mt < 4; mt++)
#pragma unroll
                for (int nt = 0; nt < 4; nt++)
                    mma8(acc[mt][nt], af[mt], bf[nt]);
        }

        if (kt + 1 < NT) {
            const int nb = (kt + 1) & 1;
            *(uint4*)(&As[nb][r0 * BKS + c0]) =
                make_uint4(f2tf(va0.x), f2tf(va0.y), f2tf(va0.z), f2tf(va0.w));
            *(uint4*)(&As[nb][(r0 + 64) * BKS + c0]) =
                make_uint4(f2tf(va1.x), f2tf(va1.y), f2tf(va1.z), f2tf(va1.w));
            *(uint4*)(&Bs[nb][r0 * BKS + c0]) =
                make_uint4(f2tf(vb0.x), f2tf(vb0.y), f2tf(vb0.z), f2tf(vb0.w));
            *(uint4*)(&Bs[nb][(r0 + 64) * BKS + c0]) =
                make_uint4(f2tf(vb1.x), f2tf(vb1.y), f2tf(vb1.z), f2tf(vb1.w));
            __syncthreads();
        }
    }

#pragma unroll
    for (int mt = 0; mt < 4; mt++) {
        const int row = bm + wm * 64 + mt * 16 + g;
#pragma unroll
        for (int nt = 0; nt < 4; nt++) {
            const int col = bn + wn * 32 + nt * 8 + 2 * t4;
            *(float2*)(C + (size_t)row * N + col) =
                make_float2(acc[mt][nt][0], acc[mt][nt][1]);
            *(float2*)(C + (size_t)(row + 8) * N + col) =
                make_float2(acc[mt][nt][2], acc[mt][nt][3]);
        }
    }
}

__global__ __launch_bounds__(256, 2)
void qkv_gemm_kernel(const float* __restrict__ x, const float* __restrict__ w)
{
    mma_gemm_nt(x, w, g_qkv, QKVN, LL);
}

__global__ __launch_bounds__(256, 2)
void out_gemm_kernel(const float* __restrict__ w, float* __restrict__ out)
{
    mma_gemm_nt(g_attn, w, out, LL, LL);
}

// ---------------------------------------------------------------------------
// Flash attention, causal, TF32 tensor cores, v2.
// grid = (S/128, H, B) with qb reversed (heavy CTAs first); 256 threads = 8
// warps, warp w owns rows 16w..16w+15 of the 128-row Q tile. KV tiles 64 keys.
// V kept row-major (no transpose), stride 72 => conflict-free B-fragment LDS.
// P stays in registers: C-frag -> A-frag repack via quad shuffles (no smem
// round trip, no extra sync). Smem 69KB => 2 CTAs/SM.
// ---------------------------------------------------------------------------
#define QTILE 128
#define AST 68
#define VST 72
#define ATTN_SMEM ((QTILE*AST + 64*AST + 64*VST) * 4)

__global__ __launch_bounds__(256, 2)
void attn_kernel()
{
    extern __shared__ unsigned sm[];
    unsigned* Qs = sm;                         // [128][68], prescaled tf32
    unsigned* Ks = sm + QTILE * AST;           // [64][68]
    unsigned* Vs = sm + QTILE * AST + 64*AST;  // [64][72], row-major V[key][d]

    const int qb   = gridDim.x - 1 - blockIdx.x;   // 0..15, heavy first
    const int h    = blockIdx.y;
    const int b    = blockIdx.z;
    const int hk   = h >> 2;
    const int tid  = threadIdx.x;
    const int lane = tid & 31;
    const int w    = tid >> 5;
    const int g    = lane >> 2;
    const int t4   = lane & 3;
    const int R0   = 16 * w + g;          // fragment row in tile (R1 = R0+8)
    const int gR0  = qb * QTILE + R0;     // global query row

    // ---- load + prescale Q (128x64) ----
    {
        const float* qbase = g_qkv + (size_t)(b * SS + qb * QTILE) * QKVN + h * DD;
#pragma unroll
        for (int i = 0; i < 8; i++) {
            const int e = tid + i * 256;
            const int r = e >> 4, c = (e & 15) << 2;
            float4 v = *(const float4*)(qbase + (size_t)r * QKVN + c);
            *(uint4*)(&Qs[r * AST + c]) =
                make_uint4(f2tf(v.x * 0.125f), f2tf(v.y * 0.125f),
                           f2tf(v.z * 0.125f), f2tf(v.w * 0.125f));
        }
    }

    float m0 = -1e30f, m1 = -1e30f, l0 = 0.f, l1 = 0.f;
    float oacc[8][4];
#pragma unroll
    for (int nt = 0; nt < 8; nt++)
#pragma unroll
        for (int r = 0; r < 4; r++) oacc[nt][r] = 0.f;

    __syncthreads();

    const int kb_max = 2 * qb + 1;
    for (int kb = 0; kb <= kb_max; kb++) {
        // ---- stage K (row-major, stride 68) and V (row-major, stride 72) ----
        const float* kbase = g_qkv + (size_t)(b * SS + kb * 64) * QKVN
                             + HH * DD + hk * DD;
#pragma unroll
        for (int i = 0; i < 4; i++) {
            const int e = tid + i * 256;
            const int r = e >> 4, c = (e & 15) << 2;
            const float* p = kbase + (size_t)r * QKVN + c;
            float4 kv = *(const float4*)(p);
            *(uint4*)(&Ks[r * AST + c]) =
                make_uint4(f2tf(kv.x), f2tf(kv.y), f2tf(kv.z), f2tf(kv.w));
            float4 vv = *(const float4*)(p + HKK * DD);
            *(uint4*)(&Vs[r * VST + c]) =
                make_uint4(f2tf(vv.x), f2tf(vv.y), f2tf(vv.z), f2tf(vv.w));
        }
        __syncthreads();

        // Warp strip fully masked by causality? (rows 16w..16w+15 all < cols)
        const bool active = (kb * 64 <= qb * QTILE + 16 * w + 15);
        if (active) {
            // ---- S = Q K^T (m16 x n64 per warp) ----
            float sacc[8][4];
#pragma unroll
            for (int nt = 0; nt < 8; nt++)
#pragma unroll
                for (int r = 0; r < 4; r++) sacc[nt][r] = 0.f;

#pragma unroll
            for (int kk = 0; kk < 8; kk++) {
                const int kp = kk * 8;
                unsigned af[4];
                af[0] = Qs[ R0      * AST + kp + t4];
                af[1] = Qs[(R0 + 8) * AST + kp + t4];
                af[2] = Qs[ R0      * AST + kp + t4 + 4];
                af[3] = Qs[(R0 + 8) * AST + kp + t4 + 4];
#pragma unroll
                for (int nt = 0; nt < 8; nt++) {
                    unsigned bf[2];
                    bf[0] = Ks[(nt * 8 + g) * AST + kp + t4];
                    bf[1] = Ks[(nt * 8 + g) * AST + kp + t4 + 4];
                    mma8(sacc[nt], af, bf);
                }
            }

            // ---- causal mask (only blocks overlapping the diagonal) ----
            if (kb * 64 + 63 > qb * QTILE + 16 * w) {
#pragma unroll
                for (int nt = 0; nt < 8; nt++) {
                    const int cc = kb * 64 + nt * 8 + 2 * t4;
                    if (cc     > gR0)     sacc[nt][0] = -1e30f;
                    if (cc + 1 > gR0)     sacc[nt][1] = -1e30f;
                    if (cc     > gR0 + 8) sacc[nt][2] = -1e30f;
                    if (cc + 1 > gR0 + 8) sacc[nt][3] = -1e30f;
                }
            }

            // ---- online softmax (rows R0, R0+8; quad reduce) ----
            float mx0 = -1e30f, mx1 = -1e30f;
#pragma unroll
            for (int nt = 0; nt < 8; nt++) {
                mx0 = fmaxf(mx0, fmaxf(sacc[nt][0], sacc[nt][1]));
                mx1 = fmaxf(mx1, fmaxf(sacc[nt][2], sacc[nt][3]));
            }
            mx0 = fmaxf(mx0, __shfl_xor_sync(0xffffffffu, mx0, 1));
            mx0 = fmaxf(mx0, __shfl_xor_sync(0xffffffffu, mx0, 2));
            mx1 = fmaxf(mx1, __shfl_xor_sync(0xffffffffu, mx1, 1));
            mx1 = fmaxf(mx1, __shfl_xor_sync(0xffffffffu, mx1, 2));

            const float mn0 = fmaxf(m0, mx0);
            const float mn1 = fmaxf(m1, mx1);
            float sum0 = 0.f, sum1 = 0.f;
#pragma unroll
            for (int nt = 0; nt < 8; nt++) {
                sacc[nt][0] = __expf(sacc[nt][0] - mn0);
                sacc[nt][1] = __expf(sacc[nt][1] - mn0);
                sacc[nt][2] = __expf(sacc[nt][2] - mn1);
                sacc[nt][3] = __expf(sacc[nt][3] - mn1);
                sum0 += sacc[nt][0] + sacc[nt][1];
                sum1 += sacc[nt][2] + sacc[nt][3];
            }
            sum0 += __shfl_xor_sync(0xffffffffu, sum0, 1);
            sum0 += __shfl_xor_sync(0xffffffffu, sum0, 2);
            sum1 += __shfl_xor_sync(0xffffffffu, sum1, 1);
            sum1 += __shfl_xor_sync(0xffffffffu, sum1, 2);

            const float a0 = __expf(m0 - mn0);
            const float a1 = __expf(m1 - mn1);
            l0 = l0 * a0 + sum0;  m0 = mn0;
            l1 = l1 * a1 + sum1;  m1 = mn1;
#pragma unroll
            for (int nt = 0; nt < 8; nt++) {
                oacc[nt][0] *= a0; oacc[nt][1] *= a0;
                oacc[nt][2] *= a1; oacc[nt][3] *= a1;
            }

            // ---- O += P*V : P repacked C-frag -> A-frag via quad shuffles.
            // P(row g, col kk*8+cc) lives in lane g*4+(cc>>1), reg (cc&1) for
            // row g / 2+(cc&1) for row g+8.
            const int sA = (lane & ~3) | (t4 >> 1);
            const int sB = sA + 2;
            const bool odd = (t4 & 1);
#pragma unroll
            for (int kk = 0; kk < 8; kk++) {
                float v0A = __shfl_sync(0xffffffffu, sacc[kk][0], sA);
                float v1A = __shfl_sync(0xffffffffu, sacc[kk][1], sA);
                float v2A = __shfl_sync(0xffffffffu, sacc[kk][2], sA);
                float v3A = __shfl_sync(0xffffffffu, sacc[kk][3], sA);
                float v0B = __shfl_sync(0xffffffffu, sacc[kk][0], sB);
                float v1B = __shfl_sync(0xffffffffu, sacc[kk][1], sB);
                float v2B = __shfl_sync(0xffffffffu, sacc[kk][2], sB);
                float v3B = __shfl_sync(0xffffffffu, sacc[kk][3], sB);
                unsigned af[4];
                af[0] = f2tf(odd ? v1A : v0A);
                af[1] = f2tf(odd ? v3A : v2A);
                af[2] = f2tf(odd ? v1B : v0B);
                af[3] = f2tf(odd ? v3B : v2B);
                const int kp = kk * 8;
#pragma unroll
                for (int nt = 0; nt < 8; nt++) {
                    unsigned bf[2];
                    bf[0] = Vs[(kp + t4)     * VST + nt * 8 + g];
                    bf[1] = Vs[(kp + t4 + 4) * VST + nt * 8 + g];
                    mma8(oacc[nt], af, bf);
                }
            }
        }
        __syncthreads();   // before next iteration overwrites Ks/Vs
    }

    // ---- normalize + store (head-major [b,s,h,d]) ----
    const float inv0 = 1.f / l0;
    const float inv1 = 1.f / l1;
    float* ob = g_attn + (size_t)(b * SS + qb * QTILE) * LL + h * DD;
#pragma unroll
    for (int nt = 0; nt < 8; nt++) {
        const int cc = nt * 8 + 2 * t4;
        *(float2*)(ob + (size_t)R0 * LL + cc) =
            make_float2(oacc[nt][0] * inv0, oacc[nt][1] * inv0);
        *(float2*)(ob + (size_t)(R0 + 8) * LL + cc) =
            make_float2(oacc[nt][2] * inv1, oacc[nt][3] * inv1);
    }
}

// ---------------------------------------------------------------------------
extern "C" void kernel_launch(void* const* d_in, const int* in_sizes, int n_in,
                              void* d_out, int out_size)
{
    const float* x = nullptr;
    const float* w_qkv = nullptr;
    const float* w_out = nullptr;
    for (int i = 0; i < n_in; i++) {
        if      (in_sizes[i] == 4194304) x     = (const float*)d_in[i];
        else if (in_sizes[i] == 3670016) w_qkv = (const float*)d_in[i];
        else if (in_sizes[i] == 1048576) w_out = (const float*)d_in[i];
    }
    float* out = (float*)d_out;

    static bool attr_set = false;
    if (!attr_set) {
        cudaFuncSetAttribute(attn_kernel,
                             cudaFuncAttributeMaxDynamicSharedMemorySize,
                             ATTN_SMEM);
        attr_set = true;
    }

    // 1) fused QKV projection (only the 1536 columns actually consumed)
    qkv_gemm_kernel<<<dim3(QKVN / 128, MROWS / 128), 256>>>(x, w_qkv);

    // 2) causal GQA flash attention (tf32 tensor cores)
    attn_kernel<<<dim3(SS / QTILE, HH, BB), 256, ATTN_SMEM>>>();

    // 3) output projection
    out_gemm_kernel<<<dim3(LL / 128, MROWS / 128), 256>>>(w_out, out);
}

// round 7
// speedup vs baseline: 3.5273x; 1.0021x over previous
#include <cuda_runtime.h>
#include <math.h>

// Problem constants
#define BB   2
#define SS   2048
#define LL   1024
#define HH   16
#define HKK  4
#define DD   64
#define MROWS (BB*SS)            // 4096
#define QKVN  ((HH + 2*HKK)*DD)  // 1536 (only the used columns of w_qkv)

// Scratch (allocation-free rule: __device__ globals)
__device__ float g_qkv [MROWS * QKVN];   // [4096][1536]: q(1024) | k(256) | v(256)
__device__ float g_attn[MROWS * LL];     // [4096][1024]: attention output, head-major

// ---------------------------------------------------------------------------
// TF32 helpers
// ---------------------------------------------------------------------------
__device__ __forceinline__ unsigned f2tf(float f) {
    unsigned u;
    asm("cvt.rna.tf32.f32 %0, %1;" : "=r"(u) : "f"(f));
    return u;
}

__device__ __forceinline__ void mma8(float* c, const unsigned* a, const unsigned* b) {
    asm volatile(
        "mma.sync.aligned.m16n8k8.row.col.f32.tf32.tf32.f32 "
        "{%0,%1,%2,%3}, {%4,%5,%6,%7}, {%8,%9}, {%0,%1,%2,%3};"
        : "+f"(c[0]), "+f"(c[1]), "+f"(c[2]), "+f"(c[3])
        : "r"(a[0]), "r"(a[1]), "r"(a[2]), "r"(a[3]),
          "r"(b[0]), "r"(b[1]));
}

// ---------------------------------------------------------------------------
// TF32 tensor-core GEMM (NT): C[M,N] = A[M,K] * B[N,K]^T
// 128x128 block, BK=16, 256 threads, warps 2(M)x4(N) -> 64x32 warp tiles.
// Smem row stride 20: fragment LDS.32 banks (20g+t4) mod 32 all distinct;
// staging STS.128 phases cover all 32 banks.
// ---------------------------------------------------------------------------
#define BKS 20

__device__ __forceinline__
void mma_gemm_nt(const float* __restrict__ A, const float* __restrict__ B,
                 float* __restrict__ C, int N, int K)
{
    __shared__ unsigned As[2][128 * BKS];
    __shared__ unsigned Bs[2][128 * BKS];

    const int bm   = blockIdx.y << 7;
    const int bn   = blockIdx.x << 7;
    const int tid  = threadIdx.x;
    const int lane = tid & 31;
    const int wid  = tid >> 5;
    const int wm   = wid >> 2;     // 0..1
    const int wn   = wid & 3;      // 0..3
    const int g    = lane >> 2;    // 0..7
    const int t4   = lane & 3;     // 0..3

    const int r0 = tid >> 2;             // 0..63
    const int c0 = (tid & 3) << 2;       // 0,4,8,12
    const float* Ag0 = A + (size_t)(bm + r0)      * K + c0;
    const float* Ag1 = A + (size_t)(bm + r0 + 64) * K + c0;
    const float* Bg0 = B + (size_t)(bn + r0)      * K + c0;
    const float* Bg1 = B + (size_t)(bn + r0 + 64) * K + c0;

    float acc[4][4][4];
#pragma unroll
    for (int mt = 0; mt < 4; mt++)
#pragma unroll
        for (int nt = 0; nt < 4; nt++)
#pragma unroll
            for (int r = 0; r < 4; r++) acc[mt][nt][r] = 0.f;

    const int NT = K >> 4;

    float4 va0 = *(const float4*)(Ag0);
    float4 va1 = *(const float4*)(Ag1);
    float4 vb0 = *(const float4*)(Bg0);
    float4 vb1 = *(const float4*)(Bg1);
    {
        *(uint4*)(&As[0][r0 * BKS + c0]) =
            make_uint4(f2tf(va0.x), f2tf(va0.y), f2tf(va0.z), f2tf(va0.w));
        *(uint4*)(&As[0][(r0 + 64) * BKS + c0]) =
            make_uint4(f2tf(va1.x), f2tf(va1.y), f2tf(va1.z), f2tf(va1.w));
        *(uint4*)(&Bs[0][r0 * BKS + c0]) =
            make_uint4(f2tf(vb0.x), f2tf(vb0.y), f2tf(vb0.z), f2tf(vb0.w));
        *(uint4*)(&Bs[0][(r0 + 64) * BKS + c0]) =
            make_uint4(f2tf(vb1.x), f2tf(vb1.y), f2tf(vb1.z), f2tf(vb1.w));
    }
    __syncthreads();

    for (int kt = 0; kt < NT; kt++) {
        const int cur = kt & 1;
        if (kt + 1 < NT) {
            const int ko = (kt + 1) << 4;
            va0 = *(const float4*)(Ag0 + ko);
            va1 = *(const float4*)(Ag1 + ko);
            vb0 = *(const float4*)(Bg0 + ko);
            vb1 = *(const float4*)(Bg1 + ko);
        }
        const unsigned* as = As[cur];
        const unsigned* bs = Bs[cur];

#pragma unroll
        for (int ks = 0; ks < 2; ks++) {
            const int kb = ks * 8;
            unsigned af[4][4], bf[4][2];
#pragma unroll
            for (int mt = 0; mt < 4; mt++) {
                const int row = wm * 64 + mt * 16 + g;
                af[mt][0] = as[ row      * BKS + kb + t4];
                af[mt][1] = as[(row + 8) * BKS + kb + t4];
                af[mt][2] = as[ row      * BKS + kb + t4 + 4];
                af[mt][3] = as[(row + 8) * BKS + kb + t4 + 4];
            }
#pragma unroll
            for (int nt = 0; nt < 4; nt++) {
                const int nr = wn * 32 + nt * 8 + g;
                bf[nt][0] = bs[nr * BKS + kb + t4];
                bf[nt][1] = bs[nr * BKS + kb + t4 + 4];
            }
#pragma unroll
            for (int mt = 0; mt < 4; mt++)
#pragma unroll
                for (int nt = 0; nt < 4; nt++)
                    mma8(acc[mt][nt], af[mt], bf[nt]);
        }

        if (kt + 1 < NT) {
            const int nb = (kt + 1) & 1;
            *(uint4*)(&As[nb][r0 * BKS + c0]) =
                make_uint4(f2tf(va0.x), f2tf(va0.y), f2tf(va0.z), f2tf(va0.w));
            *(uint4*)(&As[nb][(r0 + 64) * BKS + c0]) =
                make_uint4(f2tf(va1.x), f2tf(va1.y), f2tf(va1.z), f2tf(va1.w));
            *(uint4*)(&Bs[nb][r0 * BKS + c0]) =
                make_uint4(f2tf(vb0.x), f2tf(vb0.y), f2tf(vb0.z), f2tf(vb0.w));
            *(uint4*)(&Bs[nb][(r0 + 64) * BKS + c0]) =
                make_uint4(f2tf(vb1.x), f2tf(vb1.y), f2tf(vb1.z), f2tf(vb1.w));
            __syncthreads();
        }
    }

#pragma unroll
    for (int mt = 0; mt < 4; mt++) {
        const int row = bm + wm * 64 + mt * 16 + g;
#pragma unroll
        for (int nt = 0; nt < 4; nt++) {
            const int col = bn + wn * 32 + nt * 8 + 2 * t4;
            *(float2*)(C + (size_t)row * N + col) =
                make_float2(acc[mt][nt][0], acc[mt][nt][1]);
            *(float2*)(C + (size_t)(row + 8) * N + col) =
                make_float2(acc[mt][nt][2], acc[mt][nt][3]);
        }
    }
}

__global__ __launch_bounds__(256, 2)
void qkv_gemm_kernel(const float* __restrict__ x, const float* __restrict__ w)
{
    mma_gemm_nt(x, w, g_qkv, QKVN, LL);
}

__global__ __launch_bounds__(256, 2)
void out_gemm_kernel(const float* __restrict__ w, float* __restrict__ out)
{
    mma_gemm_nt(g_attn, w, out, LL, LL);
}

// ---------------------------------------------------------------------------
// Flash attention, causal, TF32 tensor cores, v2.
// grid = (S/128, H, B) with qb reversed (heavy CTAs first); 256 threads = 8
// warps, warp w owns rows 16w..16w+15 of the 128-row Q tile. KV tiles 64 keys.
// V kept row-major (no transpose), stride 72 => conflict-free B-fragment LDS.
// P stays in registers: C-frag -> A-frag repack via quad shuffles (no smem
// round trip, no extra sync). Smem 69KB => 2 CTAs/SM.
// ---------------------------------------------------------------------------
#define QTILE 128
#define AST 68
#define VST 72
#define ATTN_SMEM ((QTILE*AST + 64*AST + 64*VST) * 4)

__global__ __launch_bounds__(256, 2)
void attn_kernel()
{
    extern __shared__ unsigned sm[];
    unsigned* Qs = sm;                         // [128][68], prescaled tf32
    unsigned* Ks = sm + QTILE * AST;           // [64][68]
    unsigned* Vs = sm + QTILE * AST + 64*AST;  // [64][72], row-major V[key][d]

    const int qb   = gridDim.x - 1 - blockIdx.x;   // 0..15, heavy first
    const int h    = blockIdx.y;
    const int b    = blockIdx.z;
    const int hk   = h >> 2;
    const int tid  = threadIdx.x;
    const int lane = tid & 31;
    const int w    = tid >> 5;
    const int g    = lane >> 2;
    const int t4   = lane & 3;
    const int R0   = 16 * w + g;          // fragment row in tile (R1 = R0+8)
    const int gR0  = qb * QTILE + R0;     // global query row

    // ---- load + prescale Q (128x64) ----
    {
        const float* qbase = g_qkv + (size_t)(b * SS + qb * QTILE) * QKVN + h * DD;
#pragma unroll
        for (int i = 0; i < 8; i++) {
            const int e = tid + i * 256;
            const int r = e >> 4, c = (e & 15) << 2;
            float4 v = *(const float4*)(qbase + (size_t)r * QKVN + c);
            *(uint4*)(&Qs[r * AST + c]) =
                make_uint4(f2tf(v.x * 0.125f), f2tf(v.y * 0.125f),
                           f2tf(v.z * 0.125f), f2tf(v.w * 0.125f));
        }
    }

    float m0 = -1e30f, m1 = -1e30f, l0 = 0.f, l1 = 0.f;
    float oacc[8][4];
#pragma unroll
    for (int nt = 0; nt < 8; nt++)
#pragma unroll
        for (int r = 0; r < 4; r++) oacc[nt][r] = 0.f;

    __syncthreads();

    const int kb_max = 2 * qb + 1;
    for (int kb = 0; kb <= kb_max; kb++) {
        // ---- stage K (row-major, stride 68) and V (row-major, stride 72) ----
        const float* kbase = g_qkv + (size_t)(b * SS + kb * 64) * QKVN
                             + HH * DD + hk * DD;
#pragma unroll
        for (int i = 0; i < 4; i++) {
            const int e = tid + i * 256;
            const int r = e >> 4, c = (e & 15) << 2;
            const float* p = kbase + (size_t)r * QKVN + c;
            float4 kv = *(const float4*)(p);
            *(uint4*)(&Ks[r * AST + c]) =
                make_uint4(f2tf(kv.x), f2tf(kv.y), f2tf(kv.z), f2tf(kv.w));
            float4 vv = *(const float4*)(p + HKK * DD);
            *(uint4*)(&Vs[r * VST + c]) =
                make_uint4(f2tf(vv.x), f2tf(vv.y), f2tf(vv.z), f2tf(vv.w));
        }
        __syncthreads();

        // Warp strip fully masked by causality? (rows 16w..16w+15 all < cols)
        const bool active = (kb * 64 <= qb * QTILE + 16 * w + 15);
        if (active) {
            // ---- S = Q K^T (m16 x n64 per warp) ----
            float sacc[8][4];
#pragma unroll
            for (int nt = 0; nt < 8; nt++)
#pragma unroll
                for (int r = 0; r < 4; r++) sacc[nt][r] = 0.f;

#pragma unroll
            for (int kk = 0; kk < 8; kk++) {
                const int kp = kk * 8;
                unsigned af[4];
                af[0] = Qs[ R0      * AST + kp + t4];
                af[1] = Qs[(R0 + 8) * AST + kp + t4];
                af[2] = Qs[ R0      * AST + kp + t4 + 4];
                af[3] = Qs[(R0 + 8) * AST + kp + t4 + 4];
#pragma unroll
                for (int nt = 0; nt < 8; nt++) {
                    unsigned bf[2];
                    bf[0] = Ks[(nt * 8 + g) * AST + kp + t4];
                    bf[1] = Ks[(nt * 8 + g) * AST + kp + t4 + 4];
                    mma8(sacc[nt], af, bf);
                }
            }

            // ---- causal mask (only blocks overlapping the diagonal) ----
            if (kb * 64 + 63 > qb * QTILE + 16 * w) {
#pragma unroll
                for (int nt = 0; nt < 8; nt++) {
                    const int cc = kb * 64 + nt * 8 + 2 * t4;
                    if (cc     > gR0)     sacc[nt][0] = -1e30f;
                    if (cc + 1 > gR0)     sacc[nt][1] = -1e30f;
                    if (cc     > gR0 + 8) sacc[nt][2] = -1e30f;
                    if (cc + 1 > gR0 + 8) sacc[nt][3] = -1e30f;
                }
            }

            // ---- online softmax (rows R0, R0+8; quad reduce) ----
            float mx0 = -1e30f, mx1 = -1e30f;
#pragma unroll
            for (int nt = 0; nt < 8; nt++) {
                mx0 = fmaxf(mx0, fmaxf(sacc[nt][0], sacc[nt][1]));
                mx1 = fmaxf(mx1, fmaxf(sacc[nt][2], sacc[nt][3]));
            }
            mx0 = fmaxf(mx0, __shfl_xor_sync(0xffffffffu, mx0, 1));
            mx0 = fmaxf(mx0, __shfl_xor_sync(0xffffffffu, mx0, 2));
            mx1 = fmaxf(mx1, __shfl_xor_sync(0xffffffffu, mx1, 1));
            mx1 = fmaxf(mx1, __shfl_xor_sync(0xffffffffu, mx1, 2));

            const float mn0 = fmaxf(m0, mx0);
            const float mn1 = fmaxf(m1, mx1);
            float sum0 = 0.f, sum1 = 0.f;
#pragma unroll
            for (int nt = 0; nt < 8; nt++) {
                sacc[nt][0] = __expf(sacc[nt][0] - mn0);
                sacc[nt][1] = __expf(sacc[nt][1] - mn0);
                sacc[nt][2] = __expf(sacc[nt][2] - mn1);
                sacc[nt][3] = __expf(sacc[nt][3] - mn1);
                sum0 += sacc[nt][0] + sacc[nt][1];
                sum1 += sacc[nt][2] + sacc[nt][3];
            }
            sum0 += __shfl_xor_sync(0xffffffffu, sum0, 1);
            sum0 += __shfl_xor_sync(0xffffffffu, sum0, 2);
            sum1 += __shfl_xor_sync(0xffffffffu, sum1, 1);
            sum1 += __shfl_xor_sync(0xffffffffu, sum1, 2);

            const float a0 = __expf(m0 - mn0);
            const float a1 = __expf(m1 - mn1);
            l0 = l0 * a0 + sum0;  m0 = mn0;
            l1 = l1 * a1 + sum1;  m1 = mn1;
#pragma unroll
            for (int nt = 0; nt < 8; nt++) {
                oacc[nt][0] *= a0; oacc[nt][1] *= a0;
                oacc[nt][2] *= a1; oacc[nt][3] *= a1;
            }

            // ---- O += P*V : P repacked C-frag -> A-frag via quad shuffles.
            // P(row g, col kk*8+cc) lives in lane g*4+(cc>>1), reg (cc&1) for
            // row g / 2+(cc&1) for row g+8.
            const int sA = (lane & ~3) | (t4 >> 1);
            const int sB = sA + 2;
            const bool odd = (t4 & 1);
#pragma unroll
            for (int kk = 0; kk < 8; kk++) {
                float v0A = __shfl_sync(0xffffffffu, sacc[kk][0], sA);
                float v1A = __shfl_sync(0xffffffffu, sacc[kk][1], sA);
                float v2A = __shfl_sync(0xffffffffu, sacc[kk][2], sA);
                float v3A = __shfl_sync(0xffffffffu, sacc[kk][3], sA);
                float v0B = __shfl_sync(0xffffffffu, sacc[kk][0], sB);
                float v1B = __shfl_sync(0xffffffffu, sacc[kk][1], sB);
                float v2B = __shfl_sync(0xffffffffu, sacc[kk][2], sB);
                float v3B = __shfl_sync(0xffffffffu, sacc[kk][3], sB);
                unsigned af[4];
                af[0] = f2tf(odd ? v1A : v0A);
                af[1] = f2tf(odd ? v3A : v2A);
                af[2] = f2tf(odd ? v1B : v0B);
                af[3] = f2tf(odd ? v3B : v2B);
                const int kp = kk * 8;
#pragma unroll
                for (int nt = 0; nt < 8; nt++) {
                    unsigned bf[2];
                    bf[0] = Vs[(kp + t4)     * VST + nt * 8 + g];
                    bf[1] = Vs[(kp + t4 + 4) * VST + nt * 8 + g];
                    mma8(oacc[nt], af, bf);
                }
            }
        }
        __syncthreads();   // before next iteration overwrites Ks/Vs
    }

    // ---- normalize + store (head-major [b,s,h,d]) ----
    const float inv0 = 1.f / l0;
    const float inv1 = 1.f / l1;
    float* ob = g_attn + (size_t)(b * SS + qb * QTILE) * LL + h * DD;
#pragma unroll
    for (int nt = 0; nt < 8; nt++) {
        const int cc = nt * 8 + 2 * t4;
        *(float2*)(ob + (size_t)R0 * LL + cc) =
            make_float2(oacc[nt][0] * inv0, oacc[nt][1] * inv0);
        *(float2*)(ob + (size_t)(R0 + 8) * LL + cc) =
            make_float2(oacc[nt][2] * inv1, oacc[nt][3] * inv1);
    }
}

// ---------------------------------------------------------------------------
extern "C" void kernel_launch(void* const* d_in, const int* in_sizes, int n_in,
                              void* d_out, int out_size)
{
    const float* x = nullptr;
    const float* w_qkv = nullptr;
    const float* w_out = nullptr;
    for (int i = 0; i < n_in; i++) {
        if      (in_sizes[i] == 4194304) x     = (const float*)d_in[i];
        else if (in_sizes[i] == 3670016) w_qkv = (const float*)d_in[i];
        else if (in_sizes[i] == 1048576) w_out = (const float*)d_in[i];
    }
    float* out = (float*)d_out;

    static bool attr_set = false;
    if (!attr_set) {
        cudaFuncSetAttribute(attn_kernel,
                             cudaFuncAttributeMaxDynamicSharedMemorySize,
                             ATTN_SMEM);
        attr_set = true;
    }

    // 1) fused QKV projection (only the 1536 columns actually consumed)
    qkv_gemm_kernel<<<dim3(QKVN / 128, MROWS / 128), 256>>>(x, w_qkv);

    // 2) causal GQA flash attention (tf32 tensor cores)
    attn_kernel<<<dim3(SS / QTILE, HH, BB), 256, ATTN_SMEM>>>();

    // 3) output projection
    out_gemm_kernel<<<dim3(LL / 128, MROWS / 128), 256>>>(w_out, out);
}

// round 8
// speedup vs baseline: 3.5314x; 1.0012x over previous
#include <cuda_runtime.h>
#include <math.h>

// Problem constants
#define BB   2
#define SS   2048
#define LL   1024
#define HH   16
#define HKK  4
#define DD   64
#define MROWS (BB*SS)            // 4096
#define QKVN  ((HH + 2*HKK)*DD)  // 1536 (only the used columns of w_qkv)

// Scratch (allocation-free rule: __device__ globals)
__device__ float g_qkv [MROWS * QKVN];   // [4096][1536]: q(1024) | k(256) | v(256)
__device__ float g_attn[MROWS * LL];     // [4096][1024]: attention output, head-major

// ---------------------------------------------------------------------------
// TF32 helpers
// ---------------------------------------------------------------------------
__device__ __forceinline__ unsigned f2tf(float f) {
    unsigned u;
    asm("cvt.rna.tf32.f32 %0, %1;" : "=r"(u) : "f"(f));
    return u;
}

__device__ __forceinline__ void mma8(float* c, const unsigned* a, const unsigned* b) {
    asm volatile(
        "mma.sync.aligned.m16n8k8.row.col.f32.tf32.tf32.f32 "
        "{%0,%1,%2,%3}, {%4,%5,%6,%7}, {%8,%9}, {%0,%1,%2,%3};"
        : "+f"(c[0]), "+f"(c[1]), "+f"(c[2]), "+f"(c[3])
        : "r"(a[0]), "r"(a[1]), "r"(a[2]), "r"(a[3]),
          "r"(b[0]), "r"(b[1]));
}

// ---------------------------------------------------------------------------
// TF32 tensor-core GEMM (NT): C[M,N] = A[M,K] * B[N,K]^T
// 128x128 block, BK=16, 256 threads, warps 2(M)x4(N) -> 64x32 warp tiles.
// Smem row stride 20: fragment LDS.32 banks (20g+t4) mod 32 all distinct;
// staging STS.128 phases cover all 32 banks.
// ---------------------------------------------------------------------------
#define BKS 20

__device__ __forceinline__
void mma_gemm_nt(const float* __restrict__ A, const float* __restrict__ B,
                 float* __restrict__ C, int N, int K)
{
    __shared__ unsigned As[2][128 * BKS];
    __shared__ unsigned Bs[2][128 * BKS];

    const int bm   = blockIdx.y << 7;
    const int bn   = blockIdx.x << 7;
    const int tid  = threadIdx.x;
    const int lane = tid & 31;
    const int wid  = tid >> 5;
    const int wm   = wid >> 2;     // 0..1
    const int wn   = wid & 3;      // 0..3
    const int g    = lane >> 2;    // 0..7
    const int t4   = lane & 3;     // 0..3

    const int r0 = tid >> 2;             // 0..63
    const int c0 = (tid & 3) << 2;       // 0,4,8,12
    const float* Ag0 = A + (size_t)(bm + r0)      * K + c0;
    const float* Ag1 = A + (size_t)(bm + r0 + 64) * K + c0;
    const float* Bg0 = B + (size_t)(bn + r0)      * K + c0;
    const float* Bg1 = B + (size_t)(bn + r0 + 64) * K + c0;

    float acc[4][4][4];
#pragma unroll
    for (int mt = 0; mt < 4; mt++)
#pragma unroll
        for (int nt = 0; nt < 4; nt++)
#pragma unroll
            for (int r = 0; r < 4; r++) acc[mt][nt][r] = 0.f;

    const int NT = K >> 4;

    float4 va0 = *(const float4*)(Ag0);
    float4 va1 = *(const float4*)(Ag1);
    float4 vb0 = *(const float4*)(Bg0);
    float4 vb1 = *(const float4*)(Bg1);
    {
        *(uint4*)(&As[0][r0 * BKS + c0]) =
            make_uint4(f2tf(va0.x), f2tf(va0.y), f2tf(va0.z), f2tf(va0.w));
        *(uint4*)(&As[0][(r0 + 64) * BKS + c0]) =
            make_uint4(f2tf(va1.x), f2tf(va1.y), f2tf(va1.z), f2tf(va1.w));
        *(uint4*)(&Bs[0][r0 * BKS + c0]) =
            make_uint4(f2tf(vb0.x), f2tf(vb0.y), f2tf(vb0.z), f2tf(vb0.w));
        *(uint4*)(&Bs[0][(r0 + 64) * BKS + c0]) =
            make_uint4(f2tf(vb1.x), f2tf(vb1.y), f2tf(vb1.z), f2tf(vb1.w));
    }
    __syncthreads();

    for (int kt = 0; kt < NT; kt++) {
        const int cur = kt & 1;
        if (kt + 1 < NT) {
            const int ko = (kt + 1) << 4;
            va0 = *(const float4*)(Ag0 + ko);
            va1 = *(const float4*)(Ag1 + ko);
            vb0 = *(const float4*)(Bg0 + ko);
            vb1 = *(const float4*)(Bg1 + ko);
        }
        const unsigned* as = As[cur];
        const unsigned* bs = Bs[cur];

#pragma unroll
        for (int ks = 0; ks < 2; ks++) {
            const int kb = ks * 8;
            unsigned af[4][4], bf[4][2];
#pragma unroll
            for (int mt = 0; mt < 4; mt++) {
                const int row = wm * 64 + mt * 16 + g;
                af[mt][0] = as[ row      * BKS + kb + t4];
                af[mt][1] = as[(row + 8) * BKS + kb + t4];
                af[mt][2] = as[ row      * BKS + kb + t4 + 4];
                af[mt][3] = as[(row + 8) * BKS + kb + t4 + 4];
            }
#pragma unroll
            for (int nt = 0; nt < 4; nt++) {
                const int nr = wn * 32 + nt * 8 + g;
                bf[nt][0] = bs[nr * BKS + kb + t4];
                bf[nt][1] = bs[nr * BKS + kb + t4 + 4];
            }
#pragma unroll
            for (int mt = 0; mt < 4; mt++)
#pragma unroll
                for (int nt = 0; nt < 4; nt++)
                    mma8(acc[mt][nt], af[mt], bf[nt]);
        }

        if (kt + 1 < NT) {
            const int nb = (kt + 1) & 1;
            *(uint4*)(&As[nb][r0 * BKS + c0]) =
                make_uint4(f2tf(va0.x), f2tf(va0.y), f2tf(va0.z), f2tf(va0.w));
            *(uint4*)(&As[nb][(r0 + 64) * BKS + c0]) =
                make_uint4(f2tf(va1.x), f2tf(va1.y), f2tf(va1.z), f2tf(va1.w));
            *(uint4*)(&Bs[nb][r0 * BKS + c0]) =
                make_uint4(f2tf(vb0.x), f2tf(vb0.y), f2tf(vb0.z), f2tf(vb0.w));
            *(uint4*)(&Bs[nb][(r0 + 64) * BKS + c0]) =
                make_uint4(f2tf(vb1.x), f2tf(vb1.y), f2tf(vb1.z), f2tf(vb1.w));
            __syncthreads();
        }
    }

#pragma unroll
    for (int mt = 0; mt < 4; mt++) {
        const int row = bm + wm * 64 + mt * 16 + g;
#pragma unroll
        for (int nt = 0; nt < 4; nt++) {
            const int col = bn + wn * 32 + nt * 8 + 2 * t4;
            *(float2*)(C + (size_t)row * N + col) =
                make_float2(acc[mt][nt][0], acc[mt][nt][1]);
            *(float2*)(C + (size_t)(row + 8) * N + col) =
                make_float2(acc[mt][nt][2], acc[mt][nt][3]);
        }
    }
}

__global__ __launch_bounds__(256, 2)
void qkv_gemm_kernel(const float* __restrict__ x, const float* __restrict__ w)
{
    mma_gemm_nt(x, w, g_qkv, QKVN, LL);
}

__global__ __launch_bounds__(256, 2)
void out_gemm_kernel(const float* __restrict__ w, float* __restrict__ out)
{
    mma_gemm_nt(g_attn, w, out, LL, LL);
}

// ---------------------------------------------------------------------------
// Flash attention, causal, TF32 tensor cores, v2.
// grid = (S/128, H, B) with qb reversed (heavy CTAs first); 256 threads = 8
// warps, warp w owns rows 16w..16w+15 of the 128-row Q tile. KV tiles 64 keys.
// V kept row-major (no transpose), stride 72 => conflict-free B-fragment LDS.
// P stays in registers: C-frag -> A-frag repack via quad shuffles (no smem
// round trip, no extra sync). Smem 69KB => 2 CTAs/SM.
// ---------------------------------------------------------------------------
#define QTILE 128
#define AST 68
#define VST 72
#define ATTN_SMEM ((QTILE*AST + 64*AST + 64*VST) * 4)

__global__ __launch_bounds__(256, 2)
void attn_kernel()
{
    extern __shared__ unsigned sm[];
    unsigned* Qs = sm;                         // [128][68], prescaled tf32
    unsigned* Ks = sm + QTILE * AST;           // [64][68]
    unsigned* Vs = sm + QTILE * AST + 64*AST;  // [64][72], row-major V[key][d]

    const int qb   = gridDim.x - 1 - blockIdx.x;   // 0..15, heavy first
    const int h    = blockIdx.y;
    const int b    = blockIdx.z;
    const int hk   = h >> 2;
    const int tid  = threadIdx.x;
    const int lane = tid & 31;
    const int w    = tid >> 5;
    const int g    = lane >> 2;
    const int t4   = lane & 3;
    const int R0   = 16 * w + g;          // fragment row in tile (R1 = R0+8)
    const int gR0  = qb * QTILE + R0;     // global query row

    // ---- load + prescale Q (128x64) ----
    {
        const float* qbase = g_qkv + (size_t)(b * SS + qb * QTILE) * QKVN + h * DD;
#pragma unroll
        for (int i = 0; i < 8; i++) {
            const int e = tid + i * 256;
            const int r = e >> 4, c = (e & 15) << 2;
            float4 v = *(const float4*)(qbase + (size_t)r * QKVN + c);
            *(uint4*)(&Qs[r * AST + c]) =
                make_uint4(f2tf(v.x * 0.125f), f2tf(v.y * 0.125f),
                           f2tf(v.z * 0.125f), f2tf(v.w * 0.125f));
        }
    }

    float m0 = -1e30f, m1 = -1e30f, l0 = 0.f, l1 = 0.f;
    float oacc[8][4];
#pragma unroll
    for (int nt = 0; nt < 8; nt++)
#pragma unroll
        for (int r = 0; r < 4; r++) oacc[nt][r] = 0.f;

    __syncthreads();

    const int kb_max = 2 * qb + 1;
    for (int kb = 0; kb <= kb_max; kb++) {
        // ---- stage K (row-major, stride 68) and V (row-major, stride 72) ----
        const float* kbase = g_qkv + (size_t)(b * SS + kb * 64) * QKVN
                             + HH * DD + hk * DD;
#pragma unroll
        for (int i = 0; i < 4; i++) {
            const int e = tid + i * 256;
            const int r = e >> 4, c = (e & 15) << 2;
            const float* p = kbase + (size_t)r * QKVN + c;
            float4 kv = *(const float4*)(p);
            *(uint4*)(&Ks[r * AST + c]) =
                make_uint4(f2tf(kv.x), f2tf(kv.y), f2tf(kv.z), f2tf(kv.w));
            float4 vv = *(const float4*)(p + HKK * DD);
            *(uint4*)(&Vs[r * VST + c]) =
                make_uint4(f2tf(vv.x), f2tf(vv.y), f2tf(vv.z), f2tf(vv.w));
        }
        __syncthreads();

        // Warp strip fully masked by causality? (rows 16w..16w+15 all < cols)
        const bool active = (kb * 64 <= qb * QTILE + 16 * w + 15);
        if (active) {
            // ---- S = Q K^T (m16 x n64 per warp) ----
            float sacc[8][4];
#pragma unroll
            for (int nt = 0; nt < 8; nt++)
#pragma unroll
                for (int r = 0; r < 4; r++) sacc[nt][r] = 0.f;

#pragma unroll
            for (int kk = 0; kk < 8; kk++) {
                const int kp = kk * 8;
                unsigned af[4];
                af[0] = Qs[ R0      * AST + kp + t4];
                af[1] = Qs[(R0 + 8) * AST + kp + t4];
                af[2] = Qs[ R0      * AST + kp + t4 + 4];
                af[3] = Qs[(R0 + 8) * AST + kp + t4 + 4];
#pragma unroll
                for (int nt = 0; nt < 8; nt++) {
                    unsigned bf[2];
                    bf[0] = Ks[(nt * 8 + g) * AST + kp + t4];
                    bf[1] = Ks[(nt * 8 + g) * AST + kp + t4 + 4];
                    mma8(sacc[nt], af, bf);
                }
            }

            // ---- causal mask (only blocks overlapping the diagonal) ----
            if (kb * 64 + 63 > qb * QTILE + 16 * w) {
#pragma unroll
                for (int nt = 0; nt < 8; nt++) {
                    const int cc = kb * 64 + nt * 8 + 2 * t4;
                    if (cc     > gR0)     sacc[nt][0] = -1e30f;
                    if (cc + 1 > gR0)     sacc[nt][1] = -1e30f;
                    if (cc     > gR0 + 8) sacc[nt][2] = -1e30f;
                    if (cc + 1 > gR0 + 8) sacc[nt][3] = -1e30f;
                }
            }

            // ---- online softmax (rows R0, R0+8; quad reduce) ----
            float mx0 = -1e30f, mx1 = -1e30f;
#pragma unroll
            for (int nt = 0; nt < 8; nt++) {
                mx0 = fmaxf(mx0, fmaxf(sacc[nt][0], sacc[nt][1]));
                mx1 = fmaxf(mx1, fmaxf(sacc[nt][2], sacc[nt][3]));
            }
            mx0 = fmaxf(mx0, __shfl_xor_sync(0xffffffffu, mx0, 1));
            mx0 = fmaxf(mx0, __shfl_xor_sync(0xffffffffu, mx0, 2));
            mx1 = fmaxf(mx1, __shfl_xor_sync(0xffffffffu, mx1, 1));
            mx1 = fmaxf(mx1, __shfl_xor_sync(0xffffffffu, mx1, 2));

            const float mn0 = fmaxf(m0, mx0);
            const float mn1 = fmaxf(m1, mx1);
            float sum0 = 0.f, sum1 = 0.f;
#pragma unroll
            for (int nt = 0; nt < 8; nt++) {
                sacc[nt][0] = __expf(sacc[nt][0] - mn0);
                sacc[nt][1] = __expf(sacc[nt][1] - mn0);
                sacc[nt][2] = __expf(sacc[nt][2] - mn1);
                sacc[nt][3] = __expf(sacc[nt][3] - mn1);
                sum0 += sacc[nt][0] + sacc[nt][1];
                sum1 += sacc[nt][2] + sacc[nt][3];
            }
            sum0 += __shfl_xor_sync(0xffffffffu, sum0, 1);
            sum0 += __shfl_xor_sync(0xffffffffu, sum0, 2);
            sum1 += __shfl_xor_sync(0xffffffffu, sum1, 1);
            sum1 += __shfl_xor_sync(0xffffffffu, sum1, 2);

            const float a0 = __expf(m0 - mn0);
            const float a1 = __expf(m1 - mn1);
            l0 = l0 * a0 + sum0;  m0 = mn0;
            l1 = l1 * a1 + sum1;  m1 = mn1;
#pragma unroll
            for (int nt = 0; nt < 8; nt++) {
                oacc[nt][0] *= a0; oacc[nt][1] *= a0;
                oacc[nt][2] *= a1; oacc[nt][3] *= a1;
            }

            // ---- O += P*V : P repacked C-frag -> A-frag via quad shuffles.
            // P(row g, col kk*8+cc) lives in lane g*4+(cc>>1), reg (cc&1) for
            // row g / 2+(cc&1) for row g+8.
            const int sA = (lane & ~3) | (t4 >> 1);
            const int sB = sA + 2;
            const bool odd = (t4 & 1);
#pragma unroll
            for (int kk = 0; kk < 8; kk++) {
                float v0A = __shfl_sync(0xffffffffu, sacc[kk][0], sA);
                float v1A = __shfl_sync(0xffffffffu, sacc[kk][1], sA);
                float v2A = __shfl_sync(0xffffffffu, sacc[kk][2], sA);
                float v3A = __shfl_sync(0xffffffffu, sacc[kk][3], sA);
                float v0B = __shfl_sync(0xffffffffu, sacc[kk][0], sB);
                float v1B = __shfl_sync(0xffffffffu, sacc[kk][1], sB);
                float v2B = __shfl_sync(0xffffffffu, sacc[kk][2], sB);
                float v3B = __shfl_sync(0xffffffffu, sacc[kk][3], sB);
                unsigned af[4];
                af[0] = f2tf(odd ? v1A : v0A);
                af[1] = f2tf(odd ? v3A : v2A);
                af[2] = f2tf(odd ? v1B : v0B);
                af[3] = f2tf(odd ? v3B : v2B);
                const int kp = kk * 8;
#pragma unroll
                for (int nt = 0; nt < 8; nt++) {
                    unsigned bf[2];
                    bf[0] = Vs[(kp + t4)     * VST + nt * 8 + g];
                    bf[1] = Vs[(kp + t4 + 4) * VST + nt * 8 + g];
                    mma8(oacc[nt], af, bf);
                }
            }
        }
        __syncthreads();   // before next iteration overwrites Ks/Vs
    }

    // ---- normalize + store (head-major [b,s,h,d]) ----
    const float inv0 = 1.f / l0;
    const float inv1 = 1.f / l1;
    float* ob = g_attn + (size_t)(b * SS + qb * QTILE) * LL + h * DD;
#pragma unroll
    for (int nt = 0; nt < 8; nt++) {
        const int cc = nt * 8 + 2 * t4;
        *(float2*)(ob + (size_t)R0 * LL + cc) =
            make_float2(oacc[nt][0] * inv0, oacc[nt][1] * inv0);
        *(float2*)(ob + (size_t)(R0 + 8) * LL + cc) =
            make_float2(oacc[nt][2] * inv1, oacc[nt][3] * inv1);
    }
}

// ---------------------------------------------------------------------------
extern "C" void kernel_launch(void* const* d_in, const int* in_sizes, int n_in,
                              void* d_out, int out_size)
{
    const float* x = nullptr;
    const float* w_qkv = nullptr;
    const float* w_out = nullptr;
    for (int i = 0; i < n_in; i++) {
        if      (in_sizes[i] == 4194304) x     = (const float*)d_in[i];
        else if (in_sizes[i] == 3670016) w_qkv = (const float*)d_in[i];
        else if (in_sizes[i] == 1048576) w_out = (const float*)d_in[i];
    }
    float* out = (float*)d_out;

    static bool attr_set = false;
    if (!attr_set) {
        cudaFuncSetAttribute(attn_kernel,
                             cudaFuncAttributeMaxDynamicSharedMemorySize,
                             ATTN_SMEM);
        attr_set = true;
    }

    // 1) fused QKV projection (only the 1536 columns actually consumed)
    qkv_gemm_kernel<<<dim3(QKVN / 128, MROWS / 128), 256>>>(x, w_qkv);

    // 2) causal GQA flash attention (tf32 tensor cores)
    attn_kernel<<<dim3(SS / QTILE, HH, BB), 256, ATTN_SMEM>>>();

    // 3) output projection
    out_gemm_kernel<<<dim3(LL / 128, MROWS / 128), 256>>>(w_out, out);
}